// round 4
// baseline (speedup 1.0000x reference)
#include <cuda_runtime.h>
#include <cuda_bf16.h>
#include <math.h>

// Problem constants (fixed by reference setup_inputs)
#define B_    64
#define Hh    80
#define Ww    80
#define HW    6400        // Hh*Ww
#define Cc    80
#define Dd    85          // 5 + C
#define Tt    50
#define CHUNKS 8
#define CELLS (HW / CHUNKS)   // 800
#define NTHREADS 256
#define GRID   (B_ * CHUNKS)  // 512

#define LAMBDA_COORD 5.0
#define LAMBDA_NOOBJ 0.5

// Global accumulators (zero at module load; last block resets them after each
// launch so every graph replay starts from zero — deterministic).
__device__ double g_xy;
__device__ double g_wh;
__device__ double g_cls;
__device__ double g_conf_obj;
__device__ double g_conf_noobj;
__device__ int    g_nobj;
__device__ unsigned int g_done;

__device__ __forceinline__ float warp_sum(float v) {
    #pragma unroll
    for (int o = 16; o > 0; o >>= 1) v += __shfl_xor_sync(0xffffffffu, v, o);
    return v;
}
__device__ __forceinline__ int warp_sum_i(int v) {
    #pragma unroll
    for (int o = 16; o > 0; o >>= 1) v += __shfl_xor_sync(0xffffffffu, v, o);
    return v;
}
__device__ __forceinline__ float warp_max(float v) {
    #pragma unroll
    for (int o = 16; o > 0; o >>= 1) v = fmaxf(v, __shfl_xor_sync(0xffffffffu, v, o));
    return v;
}

__global__ void __launch_bounds__(NTHREADS)
loss_kernel(const float* __restrict__ pred, const float* __restrict__ tgt,
            float* __restrict__ out) {
    const int b     = blockIdx.x / CHUNKS;
    const int chunk = blockIdx.x % CHUNKS;
    const int tid   = threadIdx.x;
    const int warp  = tid >> 5;
    const int lane  = tid & 31;

    __shared__ unsigned int mask[HW / 32];   // 200 words = 800 B
    __shared__ float s_obj, s_noobj;
    __shared__ int   s_cnt;
    __shared__ bool  s_last;

    if (tid == 0) { s_obj = 0.0f; s_noobj = 0.0f; s_cnt = 0; }
    for (int i = tid; i < HW / 32; i += NTHREADS) mask[i] = 0u;
    __syncthreads();

    const float* pb = pred + (size_t)b * HW * Dd;
    const float* tb = tgt  + (size_t)b * Tt * 5;

    // Build obj bitmask from the 50 targets of this batch
    if (tid < Tt) {
        float cx = tb[tid * 5 + 1];
        float cy = tb[tid * 5 + 2];
        int gx = (int)floorf(cx * (float)Ww);
        int gy = (int)floorf(cy * (float)Hh);
        int gi = gy * Ww + gx;
        atomicOr(&mask[gi >> 5], 1u << (gi & 31));
    }
    __syncthreads();

    // ---- Confidence loss over this block's cell range ----
    float sobj = 0.0f, snoobj = 0.0f;
    const int c0 = chunk * CELLS;
    #pragma unroll 8
    for (int i = c0 + tid; i < c0 + CELLS; i += NTHREADS) {
        float x = __ldg(&pb[(size_t)i * Dd + 4]);
        unsigned int mw = mask[i >> 5];
        float sp_tail = log1pf(expf(-fabsf(x)));
        if ((mw >> (i & 31)) & 1u) sobj   += fmaxf(-x, 0.0f) + sp_tail;
        else                       snoobj += fmaxf( x, 0.0f) + sp_tail;
    }
    sobj   = warp_sum(sobj);
    snoobj = warp_sum(snoobj);
    if (lane == 0) {
        atomicAdd(&s_obj, sobj);
        atomicAdd(&s_noobj, snoobj);
    }

    if (chunk == 0) {
        // ---- count distinct obj cells for this batch ----
        int cnt = 0;
        for (int i = tid; i < HW / 32; i += NTHREADS) cnt += __popc(mask[i]);
        cnt = warp_sum_i(cnt);
        if (lane == 0 && cnt) atomicAdd(&s_cnt, cnt);

        // ---- per-target losses: one warp per target ----
        float lxy = 0.0f, lwh = 0.0f, lcls = 0.0f;
        for (int t = warp; t < Tt; t += NTHREADS / 32) {
            const float* tp = tb + t * 5;
            float cidf = tp[0], cx = tp[1], cy = tp[2], w = tp[3], h = tp[4];
            int gx = (int)floorf(cx * (float)Ww);
            int gy = (int)floorf(cy * (float)Hh);
            int gi = gy * Ww + gx;
            const float* g = pb + (size_t)gi * Dd;

            // log-softmax over 80 class logits g[5..84]
            float v0 = __ldg(&g[5 + lane]);
            float v1 = __ldg(&g[5 + 32 + lane]);
            float v2 = (lane < Cc - 64) ? __ldg(&g[5 + 64 + lane]) : -INFINITY;
            float m = warp_max(fmaxf(fmaxf(v0, v1), v2));
            float se = expf(v0 - m) + expf(v1 - m) +
                       ((lane < Cc - 64) ? expf(v2 - m) : 0.0f);
            se = warp_sum(se);
            float lse = m + logf(se);

            if (lane == 0) {
                int cid = (int)cidf;
                float fx = cx * (float)Ww - (float)gx;
                float fy = cy * (float)Hh - (float)gy;
                float p0 = g[0], p1 = g[1], p2 = g[2], p3 = g[3];
                float sx = 1.0f / (1.0f + expf(-p0));
                float sy = 1.0f / (1.0f + expf(-p1));
                float dx = sx - fx, dy = sy - fy;
                lxy += 0.5f * (dx * dx + dy * dy);
                float tw = logf(w * (float)Ww + 1e-16f);
                float th = logf(h * (float)Hh + 1e-16f);
                float dw = p2 - tw, dh = p3 - th;
                lwh += 0.5f * (dw * dw + dh * dh);
                lcls += lse - g[5 + cid];
            }
        }
        if (lane == 0) {
            if (lxy != 0.0f || lwh != 0.0f || lcls != 0.0f) {
                atomicAdd(&g_xy,  (double)lxy);
                atomicAdd(&g_wh,  (double)lwh);
                atomicAdd(&g_cls, (double)lcls);
            }
        }
    }

    __syncthreads();
    if (tid == 0) {
        atomicAdd(&g_conf_obj,   (double)s_obj);
        atomicAdd(&g_conf_noobj, (double)s_noobj);
        if (chunk == 0) atomicAdd(&g_nobj, s_cnt);

        // ---- completion protocol: last block finalizes ----
        __threadfence();
        unsigned int prev = atomicAdd(&g_done, 1u);
        s_last = (prev == GRID - 1);
    }
    __syncthreads();

    if (s_last && tid == 0) {
        double n_obj = (double)(g_nobj > 0 ? g_nobj : 1);
        double n_no  = (double)(B_ * HW) - (double)g_nobj;
        if (n_no < 1.0) n_no = 1.0;
        const double num_obj = (double)(B_ * Tt);   // 3200
        double total = LAMBDA_COORD * (g_xy + g_wh) / num_obj
                     + (g_conf_obj / n_obj) / num_obj
                     + LAMBDA_NOOBJ * (g_conf_noobj / n_no) / n_no
                     + g_cls / num_obj;
        out[0] = (float)total;

        // reset for next graph replay
        g_xy = 0.0; g_wh = 0.0; g_cls = 0.0;
        g_conf_obj = 0.0; g_conf_noobj = 0.0;
        g_nobj = 0;
        __threadfence();
        g_done = 0u;
    }
}

extern "C" void kernel_launch(void* const* d_in, const int* in_sizes, int n_in,
                              void* d_out, int out_size) {
    const float* pred = (const float*)d_in[0];
    const float* tgt  = (const float*)d_in[1];
    float* out = (float*)d_out;
    (void)in_sizes; (void)n_in; (void)out_size;

    loss_kernel<<<GRID, NTHREADS>>>(pred, tgt, out);
}

// round 7
// speedup vs baseline: 1.4203x; 1.4203x over previous
#include <cuda_runtime.h>
#include <cuda_bf16.h>
#include <math.h>

// Problem constants (fixed by reference setup_inputs)
#define B_    64
#define Hh    80
#define Ww    80
#define HW    6400
#define Cc    80
#define Dd    85
#define Tt    50
#define CHUNKS 16
#define CELLS (HW / CHUNKS)   // 400
#define NTHREADS 256
#define GRID   (B_ * CHUNKS)  // 1024

#define LAMBDA_COORD 5.0
#define LAMBDA_NOOBJ 0.5

// Global accumulators (zero at module load; last block resets them after each
// launch so every graph replay starts from zero — deterministic).
__device__ double g_xy;
__device__ double g_wh;
__device__ double g_cls;
__device__ double g_conf_obj;
__device__ double g_conf_noobj;
__device__ int    g_nobj;
__device__ unsigned int g_done;

__device__ __forceinline__ float warp_sum(float v) {
    #pragma unroll
    for (int o = 16; o > 0; o >>= 1) v += __shfl_xor_sync(0xffffffffu, v, o);
    return v;
}
__device__ __forceinline__ int warp_sum_i(int v) {
    #pragma unroll
    for (int o = 16; o > 0; o >>= 1) v += __shfl_xor_sync(0xffffffffu, v, o);
    return v;
}
__device__ __forceinline__ float warp_max(float v) {
    #pragma unroll
    for (int o = 16; o > 0; o >>= 1) v = fmaxf(v, __shfl_xor_sync(0xffffffffu, v, o));
    return v;
}

__global__ void __launch_bounds__(NTHREADS)
loss_kernel(const float* __restrict__ pred, const float* __restrict__ tgt,
            float* __restrict__ out) {
    const int b     = blockIdx.x / CHUNKS;
    const int chunk = blockIdx.x % CHUNKS;
    const int tid   = threadIdx.x;
    const int warp  = tid >> 5;
    const int lane  = tid & 31;

    __shared__ unsigned int mask[HW / 32];   // 200 words
    __shared__ float s_obj, s_noobj, s_xy, s_wh, s_cls;
    __shared__ int   s_cnt;
    __shared__ bool  s_last;

    if (tid == 0) {
        s_obj = 0.0f; s_noobj = 0.0f; s_cnt = 0;
        s_xy = 0.0f; s_wh = 0.0f; s_cls = 0.0f;
    }
    for (int i = tid; i < HW / 32; i += NTHREADS) mask[i] = 0u;
    __syncthreads();

    const float* pb = pred + (size_t)b * HW * Dd;
    const float* tb = tgt  + (size_t)b * Tt * 5;

    // ---- Issue this block's conf-logit loads EARLY (overlap w/ mask build) ----
    const int c0 = chunk * CELLS;
    const int i0 = c0 + tid;
    const int i1 = i0 + NTHREADS;
    const bool v1 = (tid < CELLS - NTHREADS);   // tid < 144
    float x0 = __ldg(&pb[(size_t)i0 * Dd + 4]);
    float x1 = v1 ? __ldg(&pb[(size_t)i1 * Dd + 4]) : 0.0f;

    // ---- Build obj bitmask from the 50 targets of this batch ----
    if (tid < Tt) {
        float cx = tb[tid * 5 + 1];
        float cy = tb[tid * 5 + 2];
        int gx = (int)floorf(cx * (float)Ww);
        int gy = (int)floorf(cy * (float)Hh);
        int gi = gy * Ww + gx;
        atomicOr(&mask[gi >> 5], 1u << (gi & 31));
    }
    __syncthreads();

    // ---- Confidence loss (loads already in flight / done) ----
    float sobj = 0.0f, snoobj = 0.0f;
    {
        unsigned int mw0 = mask[i0 >> 5];
        float t0 = log1pf(__expf(-fabsf(x0)));
        if ((mw0 >> (i0 & 31)) & 1u) sobj   += fmaxf(-x0, 0.0f) + t0;
        else                         snoobj += fmaxf( x0, 0.0f) + t0;
        if (v1) {
            unsigned int mw1 = mask[i1 >> 5];
            float t1 = log1pf(__expf(-fabsf(x1)));
            if ((mw1 >> (i1 & 31)) & 1u) sobj   += fmaxf(-x1, 0.0f) + t1;
            else                         snoobj += fmaxf( x1, 0.0f) + t1;
        }
    }
    sobj   = warp_sum(sobj);
    snoobj = warp_sum(snoobj);
    if (lane == 0) {
        atomicAdd(&s_obj, sobj);
        atomicAdd(&s_noobj, snoobj);
    }

    // ---- Per-target losses: target t handled by chunk t%16, warp t/16 ----
    if (warp < 4) {
        int t = chunk + (warp << 4);
        if (t < Tt) {
            const float* tp = tb + t * 5;
            float cidf = tp[0], cx = tp[1], cy = tp[2], w = tp[3], h = tp[4];
            int gx = (int)floorf(cx * (float)Ww);
            int gy = (int)floorf(cy * (float)Hh);
            int gi = gy * Ww + gx;
            const float* g = pb + (size_t)gi * Dd;

            // log-softmax over 80 class logits g[5..84]
            float v0 = __ldg(&g[5 + lane]);
            float vv1 = __ldg(&g[5 + 32 + lane]);
            float v2 = (lane < Cc - 64) ? __ldg(&g[5 + 64 + lane]) : -INFINITY;
            float m = warp_max(fmaxf(fmaxf(v0, vv1), v2));
            float se = expf(v0 - m) + expf(vv1 - m) +
                       ((lane < Cc - 64) ? expf(v2 - m) : 0.0f);
            se = warp_sum(se);
            float lse = m + logf(se);

            if (lane == 0) {
                int cid = (int)cidf;
                float fx = cx * (float)Ww - (float)gx;
                float fy = cy * (float)Hh - (float)gy;
                float p0 = g[0], p1 = g[1], p2 = g[2], p3 = g[3];
                float sx = 1.0f / (1.0f + expf(-p0));
                float sy = 1.0f / (1.0f + expf(-p1));
                float dx = sx - fx, dy = sy - fy;
                atomicAdd(&s_xy, 0.5f * (dx * dx + dy * dy));
                float tw = logf(w * (float)Ww + 1e-16f);
                float th = logf(h * (float)Hh + 1e-16f);
                float dw = p2 - tw, dh = p3 - th;
                atomicAdd(&s_wh, 0.5f * (dw * dw + dh * dh));
                atomicAdd(&s_cls, lse - g[5 + cid]);
            }
        }
    }

    // ---- Distinct obj-cell count: one block per batch (chunk 0), warp 7 ----
    if (chunk == 0 && warp == 7) {
        int cnt = 0;
        for (int i = lane; i < HW / 32; i += 32) cnt += __popc(mask[i]);
        cnt = warp_sum_i(cnt);
        if (lane == 0) s_cnt = cnt;
    }

    __syncthreads();
    if (tid == 0) {
        atomicAdd(&g_conf_obj,   (double)s_obj);
        atomicAdd(&g_conf_noobj, (double)s_noobj);
        if (s_xy != 0.0f || s_wh != 0.0f || s_cls != 0.0f) {
            atomicAdd(&g_xy,  (double)s_xy);
            atomicAdd(&g_wh,  (double)s_wh);
            atomicAdd(&g_cls, (double)s_cls);
        }
        if (chunk == 0) atomicAdd(&g_nobj, s_cnt);

        // ---- completion protocol: last block finalizes ----
        __threadfence();
        unsigned int prev = atomicAdd(&g_done, 1u);
        s_last = (prev == GRID - 1);
    }
    __syncthreads();

    if (s_last && tid == 0) {
        double n_obj = (double)(g_nobj > 0 ? g_nobj : 1);
        double n_no  = (double)(B_ * HW) - (double)g_nobj;
        if (n_no < 1.0) n_no = 1.0;
        const double num_obj = (double)(B_ * Tt);   // 3200
        double total = LAMBDA_COORD * (g_xy + g_wh) / num_obj
                     + (g_conf_obj / n_obj) / num_obj
                     + LAMBDA_NOOBJ * (g_conf_noobj / n_no) / n_no
                     + g_cls / num_obj;
        out[0] = (float)total;

        // reset for next graph replay
        g_xy = 0.0; g_wh = 0.0; g_cls = 0.0;
        g_conf_obj = 0.0; g_conf_noobj = 0.0;
        g_nobj = 0;
        __threadfence();
        g_done = 0u;
    }
}

extern "C" void kernel_launch(void* const* d_in, const int* in_sizes, int n_in,
                              void* d_out, int out_size) {
    const float* pred = (const float*)d_in[0];
    const float* tgt  = (const float*)d_in[1];
    float* out = (float*)d_out;
    (void)in_sizes; (void)n_in; (void)out_size;

    loss_kernel<<<GRID, NTHREADS>>>(pred, tgt, out);
}